// round 10
// baseline (speedup 1.0000x reference)
#include <cuda_runtime.h>

typedef unsigned long long u64;
typedef unsigned int u32;

#define T_STEPS 2048
#define NB 8
#define NH 16
#define BH (NB*NH)
#define KF 32
#define VF 64
#define KS 128
#define VS 64

// ---- packed f32x2 helpers ----
__device__ __forceinline__ u64 pack2(float lo, float hi) {
    u64 r;
    asm("mov.b64 %0, {%1, %2};" : "=l"(r) : "r"(__float_as_uint(lo)), "r"(__float_as_uint(hi)));
    return r;
}
__device__ __forceinline__ void unpack2(u64 a, float& lo, float& hi) {
    u32 l, h;
    asm("mov.b64 {%0, %1}, %2;" : "=r"(l), "=r"(h) : "l"(a));
    lo = __uint_as_float(l); hi = __uint_as_float(h);
}
__device__ __forceinline__ u64 fma2_(u64 a, u64 b, u64 c) {
    u64 d; asm("fma.rn.f32x2 %0, %1, %2, %3;" : "=l"(d) : "l"(a), "l"(b), "l"(c)); return d;
}
__device__ __forceinline__ u64 mul2_(u64 a, u64 b) {
    u64 d; asm("mul.rn.f32x2 %0, %1, %2;" : "=l"(d) : "l"(a), "l"(b)); return d;
}

// ---- mbarrier helpers ----
__device__ __forceinline__ void mbar_init(u32 addr, u32 count) {
    asm volatile("mbarrier.init.shared.b64 [%0], %1;" :: "r"(addr), "r"(count) : "memory");
}
__device__ __forceinline__ void mbar_arrive(u32 addr) {
    asm volatile("mbarrier.arrive.release.cta.shared::cta.b64 _, [%0];" :: "r"(addr) : "memory");
}
__device__ __forceinline__ void mbar_wait(u32 addr, u32 parity) {
    asm volatile(
        "{\n\t.reg .pred P;\n\t"
        "WL%=:\n\t"
        "mbarrier.try_wait.parity.acquire.cta.shared::cta.b64 P, [%0], %1, 0x989680;\n\t"
        "@P bra WD%=;\n\t"
        "bra WL%=;\n\t"
        "WD%=:\n\t}"
        :: "r"(addr), "r"(parity) : "memory");
}
__device__ __forceinline__ void cp16(u32 dst, const void* s) {
    asm volatile("cp.async.cg.shared.global [%0], [%1], 16;" :: "r"(dst), "l"(s));
}
__device__ __forceinline__ void cp4(u32 dst, const void* s) {
    asm volatile("cp.async.ca.shared.global [%0], [%1], 4;" :: "r"(dst), "l"(s));
}

// smem per-step stage (floats) — proven R4 layout:
// [0,32) kf | [32,64) qf | [64,192) ks swizzled: chunk g at 64+(g>>1)*4+(g&1)*64
// [192,320) qs same | [320,384) vf | [384,448) vs | [448,453) scalars | pad 456
#define STEP_F 456
#define MEGA   8                 // steps per mega-stage
#define NMEGA  3                 // ring = 24 steps = 43.8 KB static smem (< 48 KB)
#define NMEGAI (T_STEPS/MEGA)    // 256 mega-iterations

// per-step register staging (software pipeline, double-buffered)
struct SR {
    float4 sc4, vf4, vs4;
    float  msv;
    u64 kf, qf;
    ulonglong2 kA, kB, qA, qB;
};

__device__ __forceinline__ void loadregs(SR& r, const float* cur, int kgp, int cg) {
    r.sc4 = *(const float4*)(cur + 448);
    r.msv = cur[452];
    r.vf4 = *(const float4*)(cur + 320 + cg*4);
    r.vs4 = *(const float4*)(cur + 384 + cg*4);
    r.kf  = *(const u64*)(cur + 2*kgp);
    r.qf  = *(const u64*)(cur + 32 + 2*kgp);
    r.kA  = *(const ulonglong2*)(cur + 64  + kgp*4);
    r.kB  = *(const ulonglong2*)(cur + 128 + kgp*4);
    r.qA  = *(const ulonglong2*)(cur + 192 + kgp*4);
    r.qB  = *(const ulonglong2*)(cur + 256 + kgp*4);
}

__global__ __launch_bounds__(288, 1)
void e90_kernel(const float* __restrict__ k_fast, const float* __restrict__ v_fast,
                const float* __restrict__ q_fast, const float* __restrict__ decay_fast,
                const float* __restrict__ k_slow, const float* __restrict__ v_slow,
                const float* __restrict__ q_slow, const float* __restrict__ decay_slow,
                const float* __restrict__ slow_gate, const float* __restrict__ mix_fast,
                const float* __restrict__ mix_slow, const float* __restrict__ S_fast0,
                const float* __restrict__ S_slow0, float* __restrict__ out)
{
    __shared__ __align__(16) float ring[NMEGA * MEGA * STEP_F];
    __shared__ __align__(8)  u64  mbar[2 * NMEGA];   // [0..2] full, [3..5] empty

    const int tid = threadIdx.x;
    const int bh  = blockIdx.x;

    const u32 sb = (u32)__cvta_generic_to_shared(ring);
    const u32 bb = (u32)__cvta_generic_to_shared(mbar);

    if (tid == 0) {
        #pragma unroll
        for (int i = 0; i < NMEGA; i++) {
            mbar_init(bb + i*8, 32);                 // full: 32 producer-lane arrives
            mbar_init(bb + (NMEGA + i)*8, 8);        // empty: 8 consumer-warp arrives
        }
    }
    __syncthreads();   // the ONLY block barrier

    if (tid >= 256) {
        // ================= PRODUCER WARP =================
        const int lane = tid - 256;
        const float* src[4];
        int off[4], strd[4], wid[4];
        #pragma unroll
        for (int r = 0; r < 4; r++) {
            int c = r*32 + lane;
            src[r] = 0; off[r] = -1; strd[r] = 0; wid[r] = 1;
            if (c < 8)        {               src[r] = k_fast + (size_t)bh*KF + c*4;  off[r] = c*4;                        strd[r] = BH*KF; }
            else if (c < 16)  { int g = c-8;  src[r] = q_fast + (size_t)bh*KF + g*4;  off[r] = 32  + g*4;                  strd[r] = BH*KF; }
            else if (c < 48)  { int g = c-16; src[r] = k_slow + (size_t)bh*KS + g*4;  off[r] = 64  + (g>>1)*4 + (g&1)*64;  strd[r] = BH*KS; }
            else if (c < 80)  { int g = c-48; src[r] = q_slow + (size_t)bh*KS + g*4;  off[r] = 192 + (g>>1)*4 + (g&1)*64;  strd[r] = BH*KS; }
            else if (c < 96)  { int g = c-80; src[r] = v_fast + (size_t)bh*VF + g*4;  off[r] = 320 + g*4;                  strd[r] = BH*VF; }
            else if (c < 112) { int g = c-96; src[r] = v_slow + (size_t)bh*VS + g*4;  off[r] = 384 + g*4;                  strd[r] = BH*VS; }
            else if (c < 117) {
                const float* a5[5] = {decay_fast, decay_slow, slow_gate, mix_fast, mix_slow};
                src[r] = a5[c-112] + bh; off[r] = 448 + (c-112); strd[r] = BH; wid[r] = 0;
            }
        }

        int sm = 0; u32 eph = 1;   // fresh empty barriers pass parity-1 wait immediately
        for (int m = 0; m < NMEGAI; m++) {
            mbar_wait(bb + (NMEGA + sm)*8, eph);     // wait stage free
            u32 stg = sb + (u32)(sm * MEGA * STEP_F) * 4u;
            #pragma unroll
            for (int s = 0; s < MEGA; s++) {
                u32 stp = stg + (u32)(s * STEP_F) * 4u;
                #pragma unroll
                for (int r = 0; r < 4; r++) {
                    if (off[r] >= 0) {
                        u32 dst = stp + (u32)off[r] * 4u;
                        if (wid[r]) cp16(dst, src[r]); else cp4(dst, src[r]);
                        src[r] += strd[r];
                    }
                }
            }
            asm volatile("cp.async.mbarrier.arrive.noinc.shared.b64 [%0];" :: "r"(bb + sm*8) : "memory");
            if (sm == NMEGA-1) { sm = 0; eph ^= 1; } else sm++;
        }
    } else {
        // ================= 8 CONSUMER WARPS =================
        const int kgp = tid & 15;   // k-group (16 groups)
        const int cg  = tid >> 4;   // column-group (16 groups of 4 columns)

        u64 Sf[4], Ss[4][4];
        {
            const float* p0 = S_fast0 + (size_t)bh*KF*VF + (size_t)(2*kgp)*VF + cg*4;
            float4 re = *(const float4*)p0;
            float4 ro = *(const float4*)(p0 + VF);
            Sf[0] = pack2(re.x, ro.x); Sf[1] = pack2(re.y, ro.y);
            Sf[2] = pack2(re.z, ro.z); Sf[3] = pack2(re.w, ro.w);
            #pragma unroll
            for (int p = 0; p < 4; p++) {
                const float* p1 = S_slow0 + (size_t)bh*KS*VS + (size_t)(8*kgp + 2*p)*VS + cg*4;
                float4 se = *(const float4*)p1;
                float4 so = *(const float4*)(p1 + VS);
                Ss[p][0] = pack2(se.x, so.x); Ss[p][1] = pack2(se.y, so.y);
                Ss[p][2] = pack2(se.z, so.z); Ss[p][3] = pack2(se.w, so.w);
            }
        }

        float* outO = out + (size_t)BH*(KF*VF + KS*VS) + (size_t)bh*VF + cg*4;
        const bool writer = (kgp == 0);
        const bool elect  = ((tid & 31) == 0);

        // pending (unreduced) output of the previous step
        u64 po01 = 0, po23 = 0;
        float* pdst = 0;

        // reduce previous step's partials across the 16 k-groups and store
        auto reduce_store = [&]() {
            u64 a01 = po01, a23 = po23;
            #pragma unroll
            for (int msk = 1; msk < 16; msk <<= 1) {
                u32 lo0, hi0, lo1, hi1;
                asm("mov.b64 {%0, %1}, %2;" : "=r"(lo0), "=r"(hi0) : "l"(a01));
                asm("mov.b64 {%0, %1}, %2;" : "=r"(lo1), "=r"(hi1) : "l"(a23));
                lo0 = __shfl_xor_sync(0xffffffffu, lo0, msk, 16);
                hi0 = __shfl_xor_sync(0xffffffffu, hi0, msk, 16);
                lo1 = __shfl_xor_sync(0xffffffffu, lo1, msk, 16);
                hi1 = __shfl_xor_sync(0xffffffffu, hi1, msk, 16);
                u64 p01, p23;
                asm("mov.b64 %0, {%1, %2};" : "=l"(p01) : "r"(lo0), "r"(hi0));
                asm("mov.b64 %0, {%1, %2};" : "=l"(p23) : "r"(lo1), "r"(hi1));
                asm("add.rn.f32x2 %0, %0, %1;" : "+l"(a01) : "l"(p01));
                asm("add.rn.f32x2 %0, %0, %1;" : "+l"(a23) : "l"(p23));
            }
            if (writer) {
                float a0, a1, a2, a3;
                unpack2(a01, a0, a1);
                unpack2(a23, a2, a3);
                *(float4*)pdst = make_float4(a0, a1, a2, a3);
            }
        };

        // one step of state math; leaves this step's partials pending
        auto compute = [&](const SR& r, bool doprev) {
            if (doprev) reduce_store();   // prev-step shuffle chain overlaps the FMAs below

            float df = r.sc4.x, ds = r.sc4.y, g = r.sc4.z, mf = r.sc4.w;
            float ms = r.msv;
            float de = 1.0f + g * (ds - 1.0f);      // g*ds + (1-g)

            u64 df2 = pack2(df, df);
            u64 de2 = pack2(de, de);

            u64 vf2[4] = { pack2(r.vf4.x, r.vf4.x), pack2(r.vf4.y, r.vf4.y),
                           pack2(r.vf4.z, r.vf4.z), pack2(r.vf4.w, r.vf4.w) };
            float w0 = g*r.vs4.x, w1 = g*r.vs4.y, w2 = g*r.vs4.z, w3 = g*r.vs4.w;
            u64 vs2[4] = { pack2(w0, w0), pack2(w1, w1), pack2(w2, w2), pack2(w3, w3) };

            u64 accf[4];
            #pragma unroll
            for (int j = 0; j < 4; j++) {
                Sf[j]   = fma2_(df2, Sf[j], mul2_(r.kf, vf2[j]));
                accf[j] = mul2_(r.qf, Sf[j]);
            }

            u64 kk[4] = { r.kA.x, r.kA.y, r.kB.x, r.kB.y };
            u64 qq[4] = { r.qA.x, r.qA.y, r.qB.x, r.qB.y };
            u64 accs[4];
            #pragma unroll
            for (int j = 0; j < 4; j++) {
                Ss[0][j] = fma2_(de2, Ss[0][j], mul2_(kk[0], vs2[j]));
                accs[j]  = mul2_(qq[0], Ss[0][j]);
            }
            #pragma unroll
            for (int p = 1; p < 4; p++) {
                #pragma unroll
                for (int j = 0; j < 4; j++) {
                    Ss[p][j] = fma2_(de2, Ss[p][j], mul2_(kk[p], vs2[j]));
                    accs[j]  = fma2_(qq[p], Ss[p][j], accs[j]);
                }
            }

            u64 mf2 = pack2(mf, mf), ms2 = pack2(ms, ms);
            float o[4];
            #pragma unroll
            for (int j = 0; j < 4; j++) {
                u64 mm = fma2_(ms2, accs[j], mul2_(mf2, accf[j]));
                float lo, hi; unpack2(mm, lo, hi);
                o[j] = lo + hi;
            }
            po01 = pack2(o[0], o[1]);
            po23 = pack2(o[2], o[3]);
            pdst = outO;
            outO += (size_t)BH * VF;
        };

        SR R[2];
        int sm = 0; u32 cph = 0;
        mbar_wait(bb + 0, 0);
        loadregs(R[0], ring, kgp, cg);

        for (int m = 0; m < NMEGAI; m++) {
            const float* base = ring + sm * MEGA * STEP_F;
            const int nsm = (sm == NMEGA-1) ? 0 : sm+1;
            const u32 nc  = (sm == NMEGA-1) ? (cph ^ 1) : cph;
            #pragma unroll
            for (int s = 0; s < MEGA; s++) {
                if (s < MEGA-1) {
                    loadregs(R[(s+1)&1], base + (s+1)*STEP_F, kgp, cg);
                } else if (m < NMEGAI-1) {
                    // cross-boundary preload: wait next stage + load its first step,
                    // both hidden under this stage's final compute below
                    mbar_wait(bb + nsm*8, nc);
                    loadregs(R[0], ring + nsm * MEGA * STEP_F, kgp, cg);
                }
                compute(R[s&1], (m > 0) || (s > 0));
            }
            if (elect) mbar_arrive(bb + (NMEGA + sm)*8);   // stage consumed (all reads done)
            sm = nsm; cph = nc;
        }
        reduce_store();   // flush final step's pending output

        // final states
        {
            float* oSf = out + (size_t)bh*KF*VF + (size_t)(2*kgp)*VF + cg*4;
            float e0,o0,e1,o1,e2,o2,e3,o3;
            unpack2(Sf[0], e0, o0); unpack2(Sf[1], e1, o1);
            unpack2(Sf[2], e2, o2); unpack2(Sf[3], e3, o3);
            *(float4*)oSf        = make_float4(e0, e1, e2, e3);
            *(float4*)(oSf + VF) = make_float4(o0, o1, o2, o3);

            #pragma unroll
            for (int p = 0; p < 4; p++) {
                float* oSs = out + (size_t)BH*KF*VF + (size_t)bh*KS*VS + (size_t)(8*kgp + 2*p)*VS + cg*4;
                float se0,so0,se1,so1,se2,so2,se3,so3;
                unpack2(Ss[p][0], se0, so0); unpack2(Ss[p][1], se1, so1);
                unpack2(Ss[p][2], se2, so2); unpack2(Ss[p][3], se3, so3);
                *(float4*)oSs        = make_float4(se0, se1, se2, se3);
                *(float4*)(oSs + VS) = make_float4(so0, so1, so2, so3);
            }
        }
    }
}

extern "C" void kernel_launch(void* const* d_in, const int* in_sizes, int n_in,
                              void* d_out, int out_size) {
    (void)in_sizes; (void)n_in; (void)out_size;
    e90_kernel<<<BH, 288>>>(
        (const float*)d_in[0],  (const float*)d_in[1],  (const float*)d_in[2],
        (const float*)d_in[3],  (const float*)d_in[4],  (const float*)d_in[5],
        (const float*)d_in[6],  (const float*)d_in[7],  (const float*)d_in[8],
        (const float*)d_in[9],  (const float*)d_in[10], (const float*)d_in[11],
        (const float*)d_in[12], (float*)d_out);
}

// round 12
// speedup vs baseline: 1.0819x; 1.0819x over previous
#include <cuda_runtime.h>

typedef unsigned long long u64;
typedef unsigned int u32;

#define T_STEPS 2048
#define NB 8
#define NH 16
#define BH (NB*NH)
#define KF 32
#define VF 64
#define KS 128
#define VS 64

// ---- packed f32x2 helpers ----
__device__ __forceinline__ u64 pack2(float lo, float hi) {
    u64 r;
    asm("mov.b64 %0, {%1, %2};" : "=l"(r) : "r"(__float_as_uint(lo)), "r"(__float_as_uint(hi)));
    return r;
}
__device__ __forceinline__ void unpack2(u64 a, float& lo, float& hi) {
    u32 l, h;
    asm("mov.b64 {%0, %1}, %2;" : "=r"(l), "=r"(h) : "l"(a));
    lo = __uint_as_float(l); hi = __uint_as_float(h);
}
__device__ __forceinline__ u64 fma2_(u64 a, u64 b, u64 c) {
    u64 d; asm("fma.rn.f32x2 %0, %1, %2, %3;" : "=l"(d) : "l"(a), "l"(b), "l"(c)); return d;
}
__device__ __forceinline__ u64 mul2_(u64 a, u64 b) {
    u64 d; asm("mul.rn.f32x2 %0, %1, %2;" : "=l"(d) : "l"(a), "l"(b)); return d;
}
__device__ __forceinline__ u64 add2_(u64 a, u64 b) {
    u64 d; asm("add.rn.f32x2 %0, %1, %2;" : "=l"(d) : "l"(a), "l"(b)); return d;
}
__device__ __forceinline__ u64 shfl_xor_u64(u64 v, int m) {
    u32 lo, hi;
    asm("mov.b64 {%0, %1}, %2;" : "=r"(lo), "=r"(hi) : "l"(v));
    lo = __shfl_xor_sync(0xffffffffu, lo, m);
    hi = __shfl_xor_sync(0xffffffffu, hi, m);
    u64 r;
    asm("mov.b64 %0, {%1, %2};" : "=l"(r) : "r"(lo), "r"(hi));
    return r;
}

// ---- mbarrier helpers ----
__device__ __forceinline__ void mbar_init(u32 addr, u32 count) {
    asm volatile("mbarrier.init.shared.b64 [%0], %1;" :: "r"(addr), "r"(count) : "memory");
}
__device__ __forceinline__ void mbar_arrive(u32 addr) {
    asm volatile("mbarrier.arrive.release.cta.shared::cta.b64 _, [%0];" :: "r"(addr) : "memory");
}
__device__ __forceinline__ void mbar_wait(u32 addr, u32 parity) {
    asm volatile(
        "{\n\t.reg .pred P;\n\t"
        "WL%=:\n\t"
        "mbarrier.try_wait.parity.acquire.cta.shared::cta.b64 P, [%0], %1, 0x989680;\n\t"
        "@P bra WD%=;\n\t"
        "bra WL%=;\n\t"
        "WD%=:\n\t}"
        :: "r"(addr), "r"(parity) : "memory");
}
__device__ __forceinline__ void cp16(u32 dst, const void* s) {
    asm volatile("cp.async.cg.shared.global [%0], [%1], 16;" :: "r"(dst), "l"(s));
}
__device__ __forceinline__ void cp4(u32 dst, const void* s) {
    asm volatile("cp.async.ca.shared.global [%0], [%1], 4;" :: "r"(dst), "l"(s));
}

// smem per-step stage (floats) — ALL NATURAL ORDER (no swizzle needed):
// [0,32) kf | [32,64) qf | [64,192) ks | [192,320) qs
// [320,384) vf | [384,448) vs | [448,453) scalars {df,ds,g,mf,ms} | pad 456
#define STEP_F 456
#define MEGA   8                 // steps per mega-stage
#define NMEGA  3                 // ring = 24 steps = 43.8 KB static smem
#define NMEGAI (T_STEPS/MEGA)    // 256 mega-iterations

// per-step register staging (double-buffered software pipeline)
struct SR {
    float4 sc4;            // df, ds, g, mf
    float  msv;            // ms
    float  kf, qf;         // fast k/q, row = lane
    float4 ks4, qs4;       // slow k/q, rows 4l..4l+3
    ulonglong2 vfA, vfB;   // v_fast cols 8w..8w+7 packed in pairs
    ulonglong2 vsA, vsB;   // v_slow cols 8w..8w+7
};

__device__ __forceinline__ void loadregs(SR& r, const float* cur, int l, int w) {
    r.sc4 = *(const float4*)(cur + 448);
    r.msv = cur[452];
    r.kf  = cur[l];
    r.qf  = cur[32 + l];
    r.ks4 = *(const float4*)(cur + 64  + 4*l);
    r.qs4 = *(const float4*)(cur + 192 + 4*l);
    r.vfA = *(const ulonglong2*)(cur + 320 + 8*w);
    r.vfB = *(const ulonglong2*)(cur + 320 + 8*w + 4);
    r.vsA = *(const ulonglong2*)(cur + 384 + 8*w);
    r.vsB = *(const ulonglong2*)(cur + 384 + 8*w + 4);
}

__global__ __launch_bounds__(288, 1)
void e90_kernel(const float* __restrict__ k_fast, const float* __restrict__ v_fast,
                const float* __restrict__ q_fast, const float* __restrict__ decay_fast,
                const float* __restrict__ k_slow, const float* __restrict__ v_slow,
                const float* __restrict__ q_slow, const float* __restrict__ decay_slow,
                const float* __restrict__ slow_gate, const float* __restrict__ mix_fast,
                const float* __restrict__ mix_slow, const float* __restrict__ S_fast0,
                const float* __restrict__ S_slow0, float* __restrict__ out)
{
    __shared__ __align__(16) float ring[NMEGA * MEGA * STEP_F];
    __shared__ __align__(8)  u64  mbar[2 * NMEGA];   // [0..2] full, [3..5] empty

    const int tid = threadIdx.x;
    const int bh  = blockIdx.x;

    const u32 sb = (u32)__cvta_generic_to_shared(ring);
    const u32 bb = (u32)__cvta_generic_to_shared(mbar);

    if (tid == 0) {
        #pragma unroll
        for (int i = 0; i < NMEGA; i++) {
            mbar_init(bb + i*8, 32);                 // full: 32 producer-lane arrives
            mbar_init(bb + (NMEGA + i)*8, 8);        // empty: 8 consumer-warp arrives
        }
    }
    __syncthreads();   // the ONLY block barrier

    if (tid >= 256) {
        // ================= PRODUCER WARP =================
        const int lane = tid - 256;
        const float* src[4];
        int off[4], strd[4], wid[4];
        #pragma unroll
        for (int r = 0; r < 4; r++) {
            int c = r*32 + lane;
            src[r] = 0; off[r] = -1; strd[r] = 0; wid[r] = 1;
            if (c < 8)        {               src[r] = k_fast + (size_t)bh*KF + c*4;  off[r] = c*4;           strd[r] = BH*KF; }
            else if (c < 16)  { int g = c-8;  src[r] = q_fast + (size_t)bh*KF + g*4;  off[r] = 32  + g*4;     strd[r] = BH*KF; }
            else if (c < 48)  { int g = c-16; src[r] = k_slow + (size_t)bh*KS + g*4;  off[r] = 64  + g*4;     strd[r] = BH*KS; }
            else if (c < 80)  { int g = c-48; src[r] = q_slow + (size_t)bh*KS + g*4;  off[r] = 192 + g*4;     strd[r] = BH*KS; }
            else if (c < 96)  { int g = c-80; src[r] = v_fast + (size_t)bh*VF + g*4;  off[r] = 320 + g*4;     strd[r] = BH*VF; }
            else if (c < 112) { int g = c-96; src[r] = v_slow + (size_t)bh*VS + g*4;  off[r] = 384 + g*4;     strd[r] = BH*VS; }
            else if (c < 117) {
                const float* a5[5] = {decay_fast, decay_slow, slow_gate, mix_fast, mix_slow};
                src[r] = a5[c-112] + bh; off[r] = 448 + (c-112); strd[r] = BH; wid[r] = 0;
            }
        }

        int sm = 0; u32 eph = 1;   // fresh empty barriers pass parity-1 wait immediately
        for (int m = 0; m < NMEGAI; m++) {
            mbar_wait(bb + (NMEGA + sm)*8, eph);     // wait stage free
            u32 stg = sb + (u32)(sm * MEGA * STEP_F) * 4u;
            #pragma unroll
            for (int s = 0; s < MEGA; s++) {
                u32 stp = stg + (u32)(s * STEP_F) * 4u;
                #pragma unroll
                for (int r = 0; r < 4; r++) {
                    if (off[r] >= 0) {
                        u32 dst = stp + (u32)off[r] * 4u;
                        if (wid[r]) cp16(dst, src[r]); else cp4(dst, src[r]);
                        src[r] += strd[r];
                    }
                }
            }
            asm volatile("cp.async.mbarrier.arrive.noinc.shared.b64 [%0];" :: "r"(bb + sm*8) : "memory");
            if (sm == NMEGA-1) { sm = 0; eph ^= 1; } else sm++;
        }
    } else {
        // ================= 8 CONSUMER WARPS =================
        // warp w owns output columns 8w..8w+7; lane l owns fast row l and slow rows 4l..4l+3
        const int w = tid >> 5;
        const int l = tid & 31;

        // states packed along COLUMNS: Sf[j] = (col 8w+2j, 8w+2j+1) of fast row l
        u64 Sf[4], Ss[4][4];
        {
            const float* p0 = S_fast0 + (size_t)bh*KF*VF + (size_t)l*VF + 8*w;
            float4 a = *(const float4*)p0;
            float4 b = *(const float4*)(p0 + 4);
            Sf[0] = pack2(a.x, a.y); Sf[1] = pack2(a.z, a.w);
            Sf[2] = pack2(b.x, b.y); Sf[3] = pack2(b.z, b.w);
            #pragma unroll
            for (int p = 0; p < 4; p++) {
                const float* p1 = S_slow0 + (size_t)bh*KS*VS + (size_t)(4*l + p)*VS + 8*w;
                float4 c = *(const float4*)p1;
                float4 d = *(const float4*)(p1 + 4);
                Ss[p][0] = pack2(c.x, c.y); Ss[p][1] = pack2(c.z, c.w);
                Ss[p][2] = pack2(d.x, d.y); Ss[p][3] = pack2(d.z, d.w);
            }
        }

        float* outO = out + (size_t)BH*(KF*VF + KS*VS) + (size_t)bh*VF + 8*w;
        const bool elect   = (l == 0);
        const bool writer  = ((l & 3) == 0);     // lanes 0,4,..,28 each write one column
        const int  wcol    = l >> 2;             // column (within the warp's 8) this lane writes
        const bool hi16    = (l & 16) != 0;
        const bool hi8     = (l & 8)  != 0;
        const bool hi4     = (l & 4)  != 0;

        auto compute = [&](const SR& r) {
            float df = r.sc4.x, ds = r.sc4.y, g = r.sc4.z, mf = r.sc4.w;
            float ms = r.msv;
            float de = 1.0f + g * (ds - 1.0f);      // g*ds + (1-g)

            u64 df2 = pack2(df, df);
            u64 de2 = pack2(de, de);
            u64 g2  = pack2(g, g);

            u64 vf2[4] = { r.vfA.x, r.vfA.y, r.vfB.x, r.vfB.y };
            u64 vs2[4] = { mul2_(g2, r.vsA.x), mul2_(g2, r.vsA.y),
                           mul2_(g2, r.vsB.x), mul2_(g2, r.vsB.y) };

            // fast state: row l, 4 col-pairs
            u64 kf2 = pack2(r.kf, r.kf);
            u64 qf2 = pack2(r.qf, r.qf);
            u64 accf[4];
            #pragma unroll
            for (int j = 0; j < 4; j++) {
                Sf[j]   = fma2_(df2, Sf[j], mul2_(kf2, vf2[j]));
                accf[j] = mul2_(qf2, Sf[j]);
            }

            // slow state: rows 4l..4l+3, 4 col-pairs
            const float ksv[4] = { r.ks4.x, r.ks4.y, r.ks4.z, r.ks4.w };
            const float qsv[4] = { r.qs4.x, r.qs4.y, r.qs4.z, r.qs4.w };
            u64 accs[4];
            {
                u64 k2 = pack2(ksv[0], ksv[0]);
                u64 q2 = pack2(qsv[0], qsv[0]);
                #pragma unroll
                for (int j = 0; j < 4; j++) {
                    Ss[0][j] = fma2_(de2, Ss[0][j], mul2_(k2, vs2[j]));
                    accs[j]  = mul2_(q2, Ss[0][j]);
                }
            }
            #pragma unroll
            for (int p = 1; p < 4; p++) {
                u64 k2 = pack2(ksv[p], ksv[p]);
                u64 q2 = pack2(qsv[p], qsv[p]);
                #pragma unroll
                for (int j = 0; j < 4; j++) {
                    Ss[p][j] = fma2_(de2, Ss[p][j], mul2_(k2, vs2[j]));
                    accs[j]  = fma2_(q2, Ss[p][j], accs[j]);
                }
            }

            // mix -> a[0..3] = packed col-pairs (cols 8w+2j, 8w+2j+1)
            u64 mf2 = pack2(mf, mf), ms2 = pack2(ms, ms);
            u64 a0 = fma2_(ms2, accs[0], mul2_(mf2, accf[0]));  // cols 0,1
            u64 a1 = fma2_(ms2, accs[1], mul2_(mf2, accf[1]));  // cols 2,3
            u64 a2 = fma2_(ms2, accs[2], mul2_(mf2, accf[2]));  // cols 4,5
            u64 a3 = fma2_(ms2, accs[3], mul2_(mf2, accf[3]));  // cols 6,7

            // ---- value-halving butterfly over 32 lanes (9 SHFL total) ----
            // stage xor16: keep 4 cols (low lanes: 0..3, high: 4..7)
            u64 sA = hi16 ? a0 : a2;            // send the half the partner keeps
            u64 sB = hi16 ? a1 : a3;
            u64 kA = hi16 ? a2 : a0;
            u64 kB = hi16 ? a3 : a1;
            kA = add2_(kA, shfl_xor_u64(sA, 16));
            kB = add2_(kB, shfl_xor_u64(sB, 16));
            // stage xor8: keep 2 cols
            u64 sC = hi8 ? kA : kB;
            u64 kC = hi8 ? kB : kA;
            kC = add2_(kC, shfl_xor_u64(sC, 8));
            // stage xor4: keep 1 col
            float x, y;
            unpack2(kC, x, y);
            float sD = hi4 ? x : y;
            float kD = hi4 ? y : x;
            kD += __shfl_xor_sync(0xffffffffu, sD, 4);
            // stages xor2, xor1: plain reduce of the single remaining value
            kD += __shfl_xor_sync(0xffffffffu, kD, 2);
            kD += __shfl_xor_sync(0xffffffffu, kD, 1);
            // lane group 4c..4c+3 now holds the full sum of column c (c = l>>2)
            if (writer) outO[wcol] = kD;
            outO += (size_t)BH * VF;
        };

        SR R[2];
        int sm = 0; u32 cph = 0;
        mbar_wait(bb + 0, 0);
        loadregs(R[0], ring, l, w);

        for (int m = 0; m < NMEGAI; m++) {
            const float* base = ring + sm * MEGA * STEP_F;
            const int nsm = (sm == NMEGA-1) ? 0 : sm+1;
            const u32 nc  = (sm == NMEGA-1) ? (cph ^ 1) : cph;
            #pragma unroll
            for (int s = 0; s < MEGA; s++) {
                if (s < MEGA-1) {
                    loadregs(R[(s+1)&1], base + (s+1)*STEP_F, l, w);
                } else if (m < NMEGAI-1) {
                    // cross-boundary preload hidden under the final compute of this stage
                    mbar_wait(bb + nsm*8, nc);
                    loadregs(R[0], ring + nsm * MEGA * STEP_F, l, w);
                }
                compute(R[s&1]);
            }
            if (elect) mbar_arrive(bb + (NMEGA + sm)*8);   // stage consumed (all reads done)
            sm = nsm; cph = nc;
        }

        // final states
        {
            float* oSf = out + (size_t)bh*KF*VF + (size_t)l*VF + 8*w;
            float a0,a1,a2,a3,b0,b1,b2,b3;
            unpack2(Sf[0], a0, a1); unpack2(Sf[1], a2, a3);
            unpack2(Sf[2], b0, b1); unpack2(Sf[3], b2, b3);
            *(float4*)oSf       = make_float4(a0, a1, a2, a3);
            *(float4*)(oSf + 4) = make_float4(b0, b1, b2, b3);

            #pragma unroll
            for (int p = 0; p < 4; p++) {
                float* oSs = out + (size_t)BH*KF*VF + (size_t)bh*KS*VS + (size_t)(4*l + p)*VS + 8*w;
                float c0,c1,c2,c3,d0,d1,d2,d3;
                unpack2(Ss[p][0], c0, c1); unpack2(Ss[p][1], c2, c3);
                unpack2(Ss[p][2], d0, d1); unpack2(Ss[p][3], d2, d3);
                *(float4*)oSs       = make_float4(c0, c1, c2, c3);
                *(float4*)(oSs + 4) = make_float4(d0, d1, d2, d3);
            }
        }
    }
}

extern "C" void kernel_launch(void* const* d_in, const int* in_sizes, int n_in,
                              void* d_out, int out_size) {
    (void)in_sizes; (void)n_in; (void)out_size;
    e90_kernel<<<BH, 288>>>(
        (const float*)d_in[0],  (const float*)d_in[1],  (const float*)d_in[2],
        (const float*)d_in[3],  (const float*)d_in[4],  (const float*)d_in[5],
        (const float*)d_in[6],  (const float*)d_in[7],  (const float*)d_in[8],
        (const float*)d_in[9],  (const float*)d_in[10], (const float*)d_in[11],
        (const float*)d_in[12], (float*)d_out);
}